// round 15
// baseline (speedup 1.0000x reference)
#include <cuda_runtime.h>
#include <cuda_fp16.h>
#include <cstdint>

// ---------------------------------------------------------------------------
// Problem constants
// ---------------------------------------------------------------------------
static constexpr int M_TOTAL = 8192;      // 4 * 2048
static constexpr int N_TOTAL = 11008;
static constexpr int K_TOTAL = 4096;

static constexpr int BM = 64;
static constexpr int BN = 256;
static constexpr int BK = 64;                 // fp16 -> 128 B per row
static constexpr int KITERS = K_TOTAL / BK;   // 64
static constexpr int THREADS = 128;           // 4 warps, 2 CTAs per SM

static constexpr int A_SUB = BM * BK * 2;     // 8 KB per kiter sub-buffer
static constexpr int B_STAGE = BN * BK * 2;   // 32 KB
static constexpr int SMEM_BYTES = 4 * A_SUB + 2 * B_STAGE + 1024;  // 99328 -> 2 CTAs/SM

static constexpr int PID_N = N_TOTAL / BN;    // 43
static constexpr int GROUP_M = 16;            // CTA raster group (wave set ~46MB < L2)
static constexpr int N_TILES = (M_TOTAL / BM) * PID_N;   // 5504

// prepass: 2 x 16B units per thread
static constexpr int X_UNITS = 33554432 / 4;          // 8388608 float4
static constexpr int W_UNITS = 45088768 / 4;          // 11272192 int4
static constexpr int X_BLOCKS = X_UNITS / 2 / 256;    // 16384
static constexpr int W_BLOCKS = W_UNITS / 2 / 256;    // 22016

// ---------------------------------------------------------------------------
// Scratch (device globals: allocation-free)
// ---------------------------------------------------------------------------
__device__ __half g_xh[(size_t)M_TOTAL * K_TOTAL];   // 67 MB, fp16 x
__device__ __half g_wh[(size_t)N_TOTAL * K_TOTAL];   // 90 MB, fp16 dequant W

__constant__ float c_nf4[16] = {
    -1.0f, -0.6961928009986877f, -0.5250730514526367f, -0.39491748809814453f,
    -0.28444138169288635f, -0.18477343022823334f, -0.09105003625154495f, 0.0f,
    0.07958029955625534f, 0.16093020141124725f, 0.24611230194568634f,
    0.33791524171829224f, 0.44070982933044434f, 0.5626170039176941f,
    0.7229568362236023f, 1.0f};

// ---------------------------------------------------------------------------
// Helpers (baseline PTX only; sm_103 virtual target has no tcgen05)
// ---------------------------------------------------------------------------
__device__ __forceinline__ uint32_t smem_u32(const void* p) {
    uint32_t a;
    asm("{ .reg .u64 t; cvta.to.shared.u64 t, %1; cvt.u32.u64 %0, t; }" : "=r"(a) : "l"(p));
    return a;
}

__device__ __forceinline__ void cp16(uint32_t dst, const void* src) {
    asm volatile("cp.async.cg.shared.global [%0], [%1], 16;" :: "r"(dst), "l"(src));
}
__device__ __forceinline__ void cp_commit() {
    asm volatile("cp.async.commit_group;" ::: "memory");
}
template <int N>
__device__ __forceinline__ void cp_wait() {
    asm volatile("cp.async.wait_group %0;" :: "n"(N) : "memory");
}

__device__ __forceinline__ void ldsm4(uint32_t* r, uint32_t addr) {
    asm volatile("ldmatrix.sync.aligned.m8n8.x4.shared.b16 {%0,%1,%2,%3}, [%4];"
                 : "=r"(r[0]), "=r"(r[1]), "=r"(r[2]), "=r"(r[3]) : "r"(addr));
}

__device__ __forceinline__ void mma_f16(float* c, const uint32_t* a,
                                        uint32_t b0, uint32_t b1) {
    asm volatile(
        "mma.sync.aligned.m16n8k16.row.col.f32.f16.f16.f32 "
        "{%0,%1,%2,%3}, {%4,%5,%6,%7}, {%8,%9}, {%0,%1,%2,%3};"
        : "+f"(c[0]), "+f"(c[1]), "+f"(c[2]), "+f"(c[3])
        : "r"(a[0]), "r"(a[1]), "r"(a[2]), "r"(a[3]), "r"(b0), "r"(b1));
}

// SW128 swizzle on (row*128 + colb)
#define SWZ(row, colb) ((uint32_t)(row) * 128u + ((uint32_t)(colb) ^ ((((uint32_t)(row)) & 7u) << 4)))

// grouped rasterization: GROUP_M m-tiles share each B n-column within a wave
__device__ __forceinline__ void tile_coords(int t, int& m0, int& n0) {
    int group = t / (GROUP_M * PID_N);
    int local = t % (GROUP_M * PID_N);
    int pid_m = group * GROUP_M + (local & (GROUP_M - 1));
    int pid_n = local >> 4;                    // GROUP_M = 16
    m0 = pid_m * BM;
    n0 = pid_n * BN;
}

// ---------------------------------------------------------------------------
// Kernel 1 (fused prepass): x -> fp16, NF4 dequant W -> fp16, and init the
// remainder tiles' output region to bias (split-K pieces atomicAdd into it).
// ---------------------------------------------------------------------------
__global__ void __launch_bounds__(256) prepass_kernel(const float* __restrict__ x,
                                                      const int* __restrict__ q,
                                                      const float* __restrict__ sc,
                                                      const float* __restrict__ bias,
                                                      float* __restrict__ out,
                                                      int n_reg) {
    if (blockIdx.x < X_BLOCKS) {
        size_t i = ((size_t)blockIdx.x * 256 + threadIdx.x) * 2;   // float4 index
        float4 v0 = reinterpret_cast<const float4*>(x)[i];
        float4 v1 = reinterpret_cast<const float4*>(x)[i + 1];
        __half2 a0 = __floats2half2_rn(v0.x, v0.y);
        __half2 a1 = __floats2half2_rn(v0.z, v0.w);
        __half2 a2 = __floats2half2_rn(v1.x, v1.y);
        __half2 a3 = __floats2half2_rn(v1.z, v1.w);
        uint4 o = make_uint4(*reinterpret_cast<uint32_t*>(&a0),
                             *reinterpret_cast<uint32_t*>(&a1),
                             *reinterpret_cast<uint32_t*>(&a2),
                             *reinterpret_cast<uint32_t*>(&a3));
        reinterpret_cast<uint4*>(g_xh)[i >> 1] = o;
    } else if (blockIdx.x < X_BLOCKS + W_BLOCKS) {
        float tv = c_nf4[threadIdx.x & 15];                  // lane l holds nf4[l&15]
        size_t i = ((size_t)(blockIdx.x - X_BLOCKS) * 256 + threadIdx.x) * 2; // int4 idx
        int4 q0 = reinterpret_cast<const int4*>(q)[i];
        int4 q1 = reinterpret_cast<const int4*>(q)[i + 1];
        float s = __ldg(sc + (i >> 5));      // packs 2j,2j+1 share the 128-elem group
        float w0 = __shfl_sync(0xffffffffu, tv, q0.x & 15) * s;
        float w1 = __shfl_sync(0xffffffffu, tv, q0.y & 15) * s;
        float w2 = __shfl_sync(0xffffffffu, tv, q0.z & 15) * s;
        float w3 = __shfl_sync(0xffffffffu, tv, q0.w & 15) * s;
        float w4 = __shfl_sync(0xffffffffu, tv, q1.x & 15) * s;
        float w5 = __shfl_sync(0xffffffffu, tv, q1.y & 15) * s;
        float w6 = __shfl_sync(0xffffffffu, tv, q1.z & 15) * s;
        float w7 = __shfl_sync(0xffffffffu, tv, q1.w & 15) * s;
        __half2 a0 = __floats2half2_rn(w0, w1);
        __half2 a1 = __floats2half2_rn(w2, w3);
        __half2 a2 = __floats2half2_rn(w4, w5);
        __half2 a3 = __floats2half2_rn(w6, w7);
        uint4 o = make_uint4(*reinterpret_cast<uint32_t*>(&a0),
                             *reinterpret_cast<uint32_t*>(&a1),
                             *reinterpret_cast<uint32_t*>(&a2),
                             *reinterpret_cast<uint32_t*>(&a3));
        reinterpret_cast<uint4*>(g_wh)[i >> 1] = o;
    } else {
        // init remainder tile r output to bias: 16 blocks per tile, 1 float4/thr
        int bid2 = blockIdx.x - X_BLOCKS - W_BLOCKS;
        int r = bid2 >> 4;
        int inner = ((bid2 & 15) << 8) + threadIdx.x;    // 0..4095
        int m0, n0;
        tile_coords(n_reg + r, m0, n0);
        int row = inner >> 6;                            // 0..63
        int c4 = (inner & 63) << 2;                      // col offset 0..252
        int col = n0 + c4;
        float4 v = make_float4(__ldg(bias + col), __ldg(bias + col + 1),
                               __ldg(bias + col + 2), __ldg(bias + col + 3));
        *reinterpret_cast<float4*>(out + (size_t)(m0 + row) * N_TOTAL + col) = v;
    }
}

// ---------------------------------------------------------------------------
// Shared tile-load helpers
// ---------------------------------------------------------------------------
__device__ __forceinline__ void load_A(int kiter, int sub, int m0,
                                       uint32_t a_smem, int tid) {
    const __half* asrc = g_xh + (size_t)m0 * K_TOTAL + kiter * BK;
    uint32_t adst = a_smem + sub * A_SUB;
#pragma unroll
    for (int it = 0; it < 4; it++) {                 // 512 16B chunks / 128 thr
        int idx = tid + it * THREADS;
        int r = idx >> 3, ch = idx & 7;
        cp16(adst + SWZ(r, ch * 16), asrc + (size_t)r * K_TOTAL + ch * 8);
    }
}

// warp-sliced: warp w loads (and later reads) only B rows [64w, 64w+64)
__device__ __forceinline__ void load_B(int kiter, int s, int n0,
                                       uint32_t b_smem, int wid, int lane) {
    const __half* bsrc = g_wh + (size_t)n0 * K_TOTAL + kiter * BK;
    uint32_t bdst = b_smem + s * B_STAGE;
#pragma unroll
    for (int it = 0; it < 16; it++) {                // 512 chunks / 32 lanes
        int c = lane + it * 32;
        int r = wid * 64 + (c >> 3), ch = c & 7;
        cp16(bdst + SWZ(r, ch * 16), bsrc + (size_t)r * K_TOTAL + ch * 8);
    }
}

// ---------------------------------------------------------------------------
// Kernel 2: persistent mma.sync fp16 GEMM over the first n_reg tiles.
// R13 structure verbatim; n_reg is uniform across CTAs (n_reg % grid == 0).
// ---------------------------------------------------------------------------
__global__ void __launch_bounds__(THREADS, 2) gemm_f16_kernel(const float* __restrict__ bias,
                                                              float* __restrict__ out,
                                                              int n_reg) {
    extern __shared__ char smem[];
    uint32_t sb = (smem_u32(smem) + 1023u) & ~1023u;
    uint32_t a_smem = sb;
    uint32_t b_smem = sb + 4 * A_SUB;

    int tid = threadIdx.x;
    int lane = tid & 31, wid = tid >> 5;
    int warpN = wid;               // 4 warps along N, 1 along M
    int q = lane >> 3, rl = lane & 7;

    int grid = gridDim.x;
    int t = blockIdx.x;
    if (t >= n_reg) return;

    int m0, n0;
    tile_coords(t, m0, n0);
    int tn = t + grid;
    int m1 = 0, n1 = 0;
    if (tn < n_reg) tile_coords(tn, m1, n1);

    int my_tiles = (n_reg - 1 - t) / grid + 1;
    int total_gi = my_tiles * KITERS;            // multiple of 64 (even)

    // ldmatrix lane address decomposition (b16, k16 step = 32 bytes)
    uint32_t xorv = (uint32_t)rl << 4;
    uint32_t arow0 = (uint32_t)((q & 1) * 8 + rl);
    uint32_t acolq = (uint32_t)((q >> 1) * 16);
    uint32_t brow0 = (uint32_t)(warpN * 64 + (q >> 1) * 8 + rl);
    uint32_t bcolq = (uint32_t)((q & 1) * 16);

    float c[4][8][4];
#pragma unroll
    for (int i = 0; i < 4; i++)
#pragma unroll
        for (int j = 0; j < 8; j++)
#pragma unroll
            for (int k = 0; k < 4; k++) c[i][j][k] = 0.0f;

    // prologue: B(0) group, then A chunk {0,1} group -> pending = both at gi=0
    load_B(0, 0, n0, b_smem, wid, lane);
    cp_commit();
    load_A(0, 0, m0, a_smem, tid);
    load_A(1, 1, m0, a_smem, tid);
    cp_commit();

    int g = lane >> 2, tig = lane & 3;   // epilogue decomposition

#pragma unroll 1
    for (int gi = 0; gi < total_gi; gi++) {
        int k = gi & (KITERS - 1);
        int sub = gi & 3;
        int sbb = gi & 1;
        bool odd = (gi & 1) != 0;
        bool last_in_tile = (k == KITERS - 1);
        bool have_next = (gi + 1 < total_gi);
        uint32_t abase = a_smem + sub * A_SUB;
        uint32_t bbase = b_smem + sbb * B_STAGE;

        // ---- single wait: drains everything committed during gi-1 ----
        cp_wait<0>();
        __syncwarp();               // my warp's B(gi) slice + A data (own) resident

        // B phase (warp-private; ahead of the CTA barrier)
        uint32_t b0[4][4];
        {
            uint32_t colB = bcolq ^ xorv;
#pragma unroll
            for (int nb = 0; nb < 4; nb++)
                ldsm4(b0[nb], bbase + (brow0 + nb * 16) * 128 + colB);
        }
        if (have_next) {
            int ln0 = last_in_tile ? n1 : n0;
            load_B((k + 1) & (KITERS - 1), (gi + 1) & 1, ln0, b_smem, wid, lane);
        }
        cp_commit();                // B(gi+1) group (possibly empty)

        // CTA barrier only at even gi
        if (!odd) __syncthreads();

        // A ks=0 fragments, then (odd gi) issue next A chunk
        uint32_t a0[4][4];
        {
            uint32_t colA = acolq ^ xorv;
#pragma unroll
            for (int mt = 0; mt < 4; mt++)
                ldsm4(a0[mt], abase + (arow0 + mt * 16) * 128 + colA);
        }
        if (odd && have_next) {
            int lm0 = last_in_tile ? m1 : m0;
            int kk = (k + 1) & (KITERS - 1);
            int sub2 = (gi + 1) & 3;            // even: {0,1} or {2,3}
            load_A(kk, sub2, lm0, a_smem, tid);
            load_A(kk + 1, sub2 + 1, lm0, a_smem, tid);
        }
        cp_commit();                // A group (possibly empty)

        // ---- ks = 0 (both operands prefetched) ----
#pragma unroll
        for (int mt = 0; mt < 4; mt++)
#pragma unroll
            for (int nb = 0; nb < 4; nb++) {
                mma_f16(c[mt][nb * 2 + 0], a0[mt], b0[nb][0], b0[nb][1]);
                mma_f16(c[mt][nb * 2 + 1], a0[mt], b0[nb][2], b0[nb][3]);
            }
        // ---- ks = 1..3 ----
#pragma unroll
        for (int ks = 1; ks < 4; ks++) {
            uint32_t colA = ((uint32_t)(ks * 32) + acolq) ^ xorv;
            uint32_t colB = ((uint32_t)(ks * 32) + bcolq) ^ xorv;
            uint32_t a[4][4], b[4][4];
#pragma unroll
            for (int mt = 0; mt < 4; mt++)
                ldsm4(a[mt], abase + (arow0 + mt * 16) * 128 + colA);
#pragma unroll
            for (int nb = 0; nb < 4; nb++)
                ldsm4(b[nb], bbase + (brow0 + nb * 16) * 128 + colB);
#pragma unroll
            for (int mt = 0; mt < 4; mt++)
#pragma unroll
                for (int nb = 0; nb < 4; nb++) {
                    mma_f16(c[mt][nb * 2 + 0], a[mt], b[nb][0], b[nb][1]);
                    mma_f16(c[mt][nb * 2 + 1], a[mt], b[nb][2], b[nb][3]);
                }
        }

        // ---- tile epilogue: streaming stores (keep output out of L2) ----
        if (last_in_tile) {
#pragma unroll
            for (int nt = 0; nt < 8; nt++) {
                int col = n0 + warpN * 64 + nt * 8 + tig * 2;
                float bx = __ldg(bias + col);
                float by = __ldg(bias + col + 1);
#pragma unroll
                for (int mt = 0; mt < 4; mt++) {
                    size_t row = (size_t)m0 + mt * 16 + g;
                    float2 v0 = make_float2(c[mt][nt][0] + bx, c[mt][nt][1] + by);
                    float2 v1 = make_float2(c[mt][nt][2] + bx, c[mt][nt][3] + by);
                    __stcs(reinterpret_cast<float2*>(out + row * N_TOTAL + col), v0);
                    __stcs(reinterpret_cast<float2*>(out + (row + 8) * N_TOTAL + col), v1);
                    c[mt][nt][0] = 0.0f; c[mt][nt][1] = 0.0f;
                    c[mt][nt][2] = 0.0f; c[mt][nt][3] = 0.0f;
                }
            }
            m0 = m1; n0 = n1;
            tn += grid;
            if (tn < n_reg) tile_coords(tn, m1, n1);
        }
    }
}

// ---------------------------------------------------------------------------
// Kernel 3: split-K tail over the remainder tiles (separate kernel so its
// codegen cannot perturb the main GEMM loop).  Piece t covers tile
// n_reg + t/split, kiters [ (t%split)*pk, ... +pk ).  Accumulates into the
// bias-initialized output via atomicAdd.
// ---------------------------------------------------------------------------
__global__ void __launch_bounds__(THREADS, 2) gemm_tail_kernel(float* __restrict__ out,
                                                               int n_reg, int split) {
    extern __shared__ char smem[];
    uint32_t sb = (smem_u32(smem) + 1023u) & ~1023u;
    uint32_t a_smem = sb;
    uint32_t b_smem = sb + 4 * A_SUB;

    int tid = threadIdx.x;
    int lane = tid & 31, wid = tid >> 5;
    int warpN = wid;
    int q = lane >> 3, rl = lane & 7;
    int t = blockIdx.x;

    uint32_t xorv = (uint32_t)rl << 4;
    uint32_t arow0 = (uint32_t)((q & 1) * 8 + rl);
    uint32_t acolq = (uint32_t)((q >> 1) * 16);
    uint32_t brow0 = (uint32_t)(warpN * 64 + (q >> 1) * 8 + rl);
    uint32_t bcolq = (uint32_t)((q & 1) * 16);
    int g = lane >> 2, tig = lane & 3;

    int pk = KITERS / split;                 // piece kiters (even)
    int pm0, pn0;
    tile_coords(n_reg + t / split, pm0, pn0);
    int koff = (t % split) * pk;

    float c[4][8][4];
#pragma unroll
    for (int i = 0; i < 4; i++)
#pragma unroll
        for (int j = 0; j < 8; j++)
#pragma unroll
            for (int k = 0; k < 4; k++) c[i][j][k] = 0.0f;

    load_B(koff, 0, pn0, b_smem, wid, lane);
    cp_commit();
    load_A(koff, 0, pm0, a_smem, tid);
    load_A(koff + 1, 1, pm0, a_smem, tid);
    cp_commit();

#pragma unroll 1
    for (int gi = 0; gi < pk; gi++) {
        int sub = gi & 3;
        int sbb = gi & 1;
        bool odd = (gi & 1) != 0;
        bool have_next = (gi + 1 < pk);
        uint32_t abase = a_smem + sub * A_SUB;
        uint32_t bbase = b_smem + sbb * B_STAGE;

        cp_wait<0>();
        __syncwarp();

        uint32_t b0[4][4];
        {
            uint32_t colB = bcolq ^ xorv;
#pragma unroll
            for (int nb = 0; nb < 4; nb++)
                ldsm4(b0[nb], bbase + (brow0 + nb * 16) * 128 + colB);
        }
        if (have_next) load_B(koff + gi + 1, (gi + 1) & 1, pn0, b_smem, wid, lane);
        cp_commit();

        if (!odd) __syncthreads();

        uint32_t a0[4][4];
        {
            uint32_t colA = acolq ^ xorv;
#pragma unroll
            for (int mt = 0; mt < 4; mt++)
                ldsm4(a0[mt], abase + (arow0 + mt * 16) * 128 + colA);
        }
        if (odd && have_next) {
            int sub2 = (gi + 1) & 3;
            load_A(koff + gi + 1, sub2, pm0, a_smem, tid);
            load_A(koff + gi + 2, sub2 + 1, pm0, a_smem, tid);
        }
        cp_commit();

#pragma unroll
        for (int mt = 0; mt < 4; mt++)
#pragma unroll
            for (int nb = 0; nb < 4; nb++) {
                mma_f16(c[mt][nb * 2 + 0], a0[mt], b0[nb][0], b0[nb][1]);
                mma_f16(c[mt][nb * 2 + 1], a0[mt], b0[nb][2], b0[nb][3]);
            }
#pragma unroll
        for (int ks = 1; ks < 4; ks++) {
            uint32_t colA = ((uint32_t)(ks * 32) + acolq) ^ xorv;
            uint32_t colB = ((uint32_t)(ks * 32) + bcolq) ^ xorv;
            uint32_t a[4][4], b[4][4];
#pragma unroll
            for (int mt = 0; mt < 4; mt++)
                ldsm4(a[mt], abase + (arow0 + mt * 16) * 128 + colA);
#pragma unroll
            for (int nb = 0; nb < 4; nb++)
                ldsm4(b[nb], bbase + (brow0 + nb * 16) * 128 + colB);
#pragma unroll
            for (int mt = 0; mt < 4; mt++)
#pragma unroll
                for (int nb = 0; nb < 4; nb++) {
                    mma_f16(c[mt][nb * 2 + 0], a[mt], b[nb][0], b[nb][1]);
                    mma_f16(c[mt][nb * 2 + 1], a[mt], b[nb][2], b[nb][3]);
                }
        }
    }

    // piece epilogue: accumulate into bias-initialized output
#pragma unroll
    for (int nt = 0; nt < 8; nt++) {
        int col = pn0 + warpN * 64 + nt * 8 + tig * 2;
#pragma unroll
        for (int mt = 0; mt < 4; mt++) {
            size_t row = (size_t)pm0 + mt * 16 + g;
            atomicAdd(out + row * N_TOTAL + col,           c[mt][nt][0]);
            atomicAdd(out + row * N_TOTAL + col + 1,       c[mt][nt][1]);
            atomicAdd(out + (row + 8) * N_TOTAL + col,     c[mt][nt][2]);
            atomicAdd(out + (row + 8) * N_TOTAL + col + 1, c[mt][nt][3]);
        }
    }
}

// ---------------------------------------------------------------------------
// Launch
// ---------------------------------------------------------------------------
extern "C" void kernel_launch(void* const* d_in, const int* in_sizes, int n_in,
                              void* d_out, int out_size) {
    const float* x = nullptr;
    const int* wq = nullptr;
    const float* ws = nullptr;
    const float* bias = nullptr;
    for (int i = 0; i < n_in; i++) {
        switch (in_sizes[i]) {
            case 33554432: x    = (const float*)d_in[i]; break;  // 4*2048*4096
            case 45088768: wq   = (const int*)d_in[i];   break;  // 11008*4096
            case 352256:   ws   = (const float*)d_in[i]; break;  // groups
            case 11008:    bias = (const float*)d_in[i]; break;
        }
    }

    cudaFuncSetAttribute(gemm_f16_kernel,
                         cudaFuncAttributeMaxDynamicSharedMemorySize, SMEM_BYTES);
    cudaFuncSetAttribute(gemm_tail_kernel,
                         cudaFuncAttributeMaxDynamicSharedMemorySize, SMEM_BYTES);

    int dev = 0, sms = 152;
    cudaGetDevice(&dev);
    cudaDeviceGetAttribute(&sms, cudaDevAttrMultiProcessorCount, dev);

    int grid = 2 * sms;                        // persistent: 2 CTAs per SM
    if (grid > N_TILES) grid = N_TILES;

    int per = N_TILES / grid;                  // regular tiles per CTA
    int n_reg = per * grid;
    int rem = N_TILES - n_reg;                 // < grid  (32 at grid=304)
    int split = 1;
    if (rem > 0) {
        if (rem * 4 <= grid) split = 4;        // pk = 16 (even)
        else if (rem * 2 <= grid) split = 2;   // pk = 32
    }

    prepass_kernel<<<X_BLOCKS + W_BLOCKS + rem * 16, 256>>>(x, wq, ws, bias,
                                                            (float*)d_out, n_reg);

    if (rem > 0)
        gemm_tail_kernel<<<rem * split, THREADS, SMEM_BYTES>>>((float*)d_out,
                                                               n_reg, split);

    gemm_f16_kernel<<<grid, THREADS, SMEM_BYTES>>>(bias, (float*)d_out, n_reg);
    (void)out_size;
}

// round 16
// speedup vs baseline: 1.0703x; 1.0703x over previous
#include <cuda_runtime.h>
#include <cuda_fp16.h>
#include <cstdint>

// ---------------------------------------------------------------------------
// Problem constants (ALL compile-time; GB300 = 152 SMs -> GRID = 304)
// ---------------------------------------------------------------------------
static constexpr int M_TOTAL = 8192;      // 4 * 2048
static constexpr int N_TOTAL = 11008;
static constexpr int K_TOTAL = 4096;

static constexpr int BM = 64;
static constexpr int BN = 256;
static constexpr int BK = 64;                 // fp16 -> 128 B per row
static constexpr int KITERS = K_TOTAL / BK;   // 64
static constexpr int THREADS = 128;           // 4 warps, 2 CTAs per SM

static constexpr int A_SUB = BM * BK * 2;     // 8 KB per kiter sub-buffer
static constexpr int B_STAGE = BN * BK * 2;   // 32 KB
static constexpr int SMEM_BYTES = 4 * A_SUB + 2 * B_STAGE + 1024;  // 99328 -> 2 CTAs/SM

static constexpr int PID_N = N_TOTAL / BN;    // 43
static constexpr int GROUP_M = 16;            // CTA raster group (wave set ~46MB < L2)
static constexpr int N_TILES = (M_TOTAL / BM) * PID_N;   // 5504

static constexpr int GRID = 304;              // 2 CTAs x 152 SMs
static constexpr int N_REG = (N_TILES / GRID) * GRID;    // 5472 = 18*304
static constexpr int REM = N_TILES - N_REG;   // 32 remainder tiles
static constexpr int SPLIT = 4;               // split-K ways -> 128 pieces
static constexpr int PIECES = REM * SPLIT;    // 128
static constexpr int PK = KITERS / SPLIT;     // 16 kiters per piece (even)

// prepass: 2 x 16B units per thread
static constexpr int X_UNITS = 33554432 / 4;          // 8388608 float4
static constexpr int W_UNITS = 45088768 / 4;          // 11272192 int4
static constexpr int X_BLOCKS = X_UNITS / 2 / 256;    // 16384
static constexpr int W_BLOCKS = W_UNITS / 2 / 256;    // 22016

// ---------------------------------------------------------------------------
// Scratch (device globals: allocation-free)
// ---------------------------------------------------------------------------
__device__ __half g_xh[(size_t)M_TOTAL * K_TOTAL];   // 67 MB, fp16 x
__device__ __half g_wh[(size_t)N_TOTAL * K_TOTAL];   // 90 MB, fp16 dequant W

__constant__ float c_nf4[16] = {
    -1.0f, -0.6961928009986877f, -0.5250730514526367f, -0.39491748809814453f,
    -0.28444138169288635f, -0.18477343022823334f, -0.09105003625154495f, 0.0f,
    0.07958029955625534f, 0.16093020141124725f, 0.24611230194568634f,
    0.33791524171829224f, 0.44070982933044434f, 0.5626170039176941f,
    0.7229568362236023f, 1.0f};

// ---------------------------------------------------------------------------
// Helpers (baseline PTX only; sm_103 virtual target has no tcgen05)
// ---------------------------------------------------------------------------
__device__ __forceinline__ uint32_t smem_u32(const void* p) {
    uint32_t a;
    asm("{ .reg .u64 t; cvta.to.shared.u64 t, %1; cvt.u32.u64 %0, t; }" : "=r"(a) : "l"(p));
    return a;
}

__device__ __forceinline__ void cp16(uint32_t dst, const void* src) {
    asm volatile("cp.async.cg.shared.global [%0], [%1], 16;" :: "r"(dst), "l"(src));
}
__device__ __forceinline__ void cp_commit() {
    asm volatile("cp.async.commit_group;" ::: "memory");
}
template <int N>
__device__ __forceinline__ void cp_wait() {
    asm volatile("cp.async.wait_group %0;" :: "n"(N) : "memory");
}

__device__ __forceinline__ void ldsm4(uint32_t* r, uint32_t addr) {
    asm volatile("ldmatrix.sync.aligned.m8n8.x4.shared.b16 {%0,%1,%2,%3}, [%4];"
                 : "=r"(r[0]), "=r"(r[1]), "=r"(r[2]), "=r"(r[3]) : "r"(addr));
}

__device__ __forceinline__ void mma_f16(float* c, const uint32_t* a,
                                        uint32_t b0, uint32_t b1) {
    asm volatile(
        "mma.sync.aligned.m16n8k16.row.col.f32.f16.f16.f32 "
        "{%0,%1,%2,%3}, {%4,%5,%6,%7}, {%8,%9}, {%0,%1,%2,%3};"
        : "+f"(c[0]), "+f"(c[1]), "+f"(c[2]), "+f"(c[3])
        : "r"(a[0]), "r"(a[1]), "r"(a[2]), "r"(a[3]), "r"(b0), "r"(b1));
}

// SW128 swizzle on (row*128 + colb)
#define SWZ(row, colb) ((uint32_t)(row) * 128u + ((uint32_t)(colb) ^ ((((uint32_t)(row)) & 7u) << 4)))

// grouped rasterization: GROUP_M m-tiles share each B n-column within a wave
__device__ __forceinline__ void tile_coords(int t, int& m0, int& n0) {
    int group = t / (GROUP_M * PID_N);
    int local = t % (GROUP_M * PID_N);
    int pid_m = group * GROUP_M + (local & (GROUP_M - 1));
    int pid_n = local >> 4;                    // GROUP_M = 16
    m0 = pid_m * BM;
    n0 = pid_n * BN;
}

// ---------------------------------------------------------------------------
// Kernel 1 (fused prepass): x -> fp16, NF4 dequant W -> fp16, and init the
// REM remainder tiles' output region to bias (split-K pieces atomicAdd into it).
// ---------------------------------------------------------------------------
__global__ void __launch_bounds__(256) prepass_kernel(const float* __restrict__ x,
                                                      const int* __restrict__ q,
                                                      const float* __restrict__ sc,
                                                      const float* __restrict__ bias,
                                                      float* __restrict__ out) {
    if (blockIdx.x < X_BLOCKS) {
        size_t i = ((size_t)blockIdx.x * 256 + threadIdx.x) * 2;   // float4 index
        float4 v0 = reinterpret_cast<const float4*>(x)[i];
        float4 v1 = reinterpret_cast<const float4*>(x)[i + 1];
        __half2 a0 = __floats2half2_rn(v0.x, v0.y);
        __half2 a1 = __floats2half2_rn(v0.z, v0.w);
        __half2 a2 = __floats2half2_rn(v1.x, v1.y);
        __half2 a3 = __floats2half2_rn(v1.z, v1.w);
        uint4 o = make_uint4(*reinterpret_cast<uint32_t*>(&a0),
                             *reinterpret_cast<uint32_t*>(&a1),
                             *reinterpret_cast<uint32_t*>(&a2),
                             *reinterpret_cast<uint32_t*>(&a3));
        reinterpret_cast<uint4*>(g_xh)[i >> 1] = o;
    } else if (blockIdx.x < X_BLOCKS + W_BLOCKS) {
        float tv = c_nf4[threadIdx.x & 15];                  // lane l holds nf4[l&15]
        size_t i = ((size_t)(blockIdx.x - X_BLOCKS) * 256 + threadIdx.x) * 2; // int4 idx
        int4 q0 = reinterpret_cast<const int4*>(q)[i];
        int4 q1 = reinterpret_cast<const int4*>(q)[i + 1];
        float s = __ldg(sc + (i >> 5));      // packs 2j,2j+1 share the 128-elem group
        float w0 = __shfl_sync(0xffffffffu, tv, q0.x & 15) * s;
        float w1 = __shfl_sync(0xffffffffu, tv, q0.y & 15) * s;
        float w2 = __shfl_sync(0xffffffffu, tv, q0.z & 15) * s;
        float w3 = __shfl_sync(0xffffffffu, tv, q0.w & 15) * s;
        float w4 = __shfl_sync(0xffffffffu, tv, q1.x & 15) * s;
        float w5 = __shfl_sync(0xffffffffu, tv, q1.y & 15) * s;
        float w6 = __shfl_sync(0xffffffffu, tv, q1.z & 15) * s;
        float w7 = __shfl_sync(0xffffffffu, tv, q1.w & 15) * s;
        __half2 a0 = __floats2half2_rn(w0, w1);
        __half2 a1 = __floats2half2_rn(w2, w3);
        __half2 a2 = __floats2half2_rn(w4, w5);
        __half2 a3 = __floats2half2_rn(w6, w7);
        uint4 o = make_uint4(*reinterpret_cast<uint32_t*>(&a0),
                             *reinterpret_cast<uint32_t*>(&a1),
                             *reinterpret_cast<uint32_t*>(&a2),
                             *reinterpret_cast<uint32_t*>(&a3));
        reinterpret_cast<uint4*>(g_wh)[i >> 1] = o;
    } else {
        // init remainder tile r output to bias: 16 blocks per tile, 1 float4/thr
        int bid2 = blockIdx.x - X_BLOCKS - W_BLOCKS;
        int r = bid2 >> 4;
        int inner = ((bid2 & 15) << 8) + threadIdx.x;    // 0..4095
        int m0, n0;
        tile_coords(N_REG + r, m0, n0);
        int row = inner >> 6;                            // 0..63
        int c4 = (inner & 63) << 2;                      // col offset 0..252
        int col = n0 + c4;
        float4 v = make_float4(__ldg(bias + col), __ldg(bias + col + 1),
                               __ldg(bias + col + 2), __ldg(bias + col + 3));
        *reinterpret_cast<float4*>(out + (size_t)(m0 + row) * N_TOTAL + col) = v;
    }
}

// ---------------------------------------------------------------------------
// Shared tile-load helpers
// ---------------------------------------------------------------------------
__device__ __forceinline__ void load_A(int kiter, int sub, int m0,
                                       uint32_t a_smem, int tid) {
    const __half* asrc = g_xh + (size_t)m0 * K_TOTAL + kiter * BK;
    uint32_t adst = a_smem + sub * A_SUB;
#pragma unroll
    for (int it = 0; it < 4; it++) {                 // 512 16B chunks / 128 thr
        int idx = tid + it * THREADS;
        int r = idx >> 3, ch = idx & 7;
        cp16(adst + SWZ(r, ch * 16), asrc + (size_t)r * K_TOTAL + ch * 8);
    }
}

// warp-sliced: warp w loads (and later reads) only B rows [64w, 64w+64)
__device__ __forceinline__ void load_B(int kiter, int s, int n0,
                                       uint32_t b_smem, int wid, int lane) {
    const __half* bsrc = g_wh + (size_t)n0 * K_TOTAL + kiter * BK;
    uint32_t bdst = b_smem + s * B_STAGE;
#pragma unroll
    for (int it = 0; it < 16; it++) {                // 512 chunks / 32 lanes
        int c = lane + it * 32;
        int r = wid * 64 + (c >> 3), ch = c & 7;
        cp16(bdst + SWZ(r, ch * 16), bsrc + (size_t)r * K_TOTAL + ch * 8);
    }
}

// ---------------------------------------------------------------------------
// Kernel 2: persistent mma.sync fp16 GEMM over the first N_REG tiles.
// Token-identical to the R13 kernel except N_TILES -> N_REG (both constexpr).
// ---------------------------------------------------------------------------
__global__ void __launch_bounds__(THREADS, 2) gemm_f16_kernel(const float* __restrict__ bias,
                                                              float* __restrict__ out) {
    extern __shared__ char smem[];
    uint32_t sb = (smem_u32(smem) + 1023u) & ~1023u;
    uint32_t a_smem = sb;
    uint32_t b_smem = sb + 4 * A_SUB;

    int tid = threadIdx.x;
    int lane = tid & 31, wid = tid >> 5;
    int warpN = wid;               // 4 warps along N, 1 along M
    int q = lane >> 3, rl = lane & 7;

    int grid = gridDim.x;
    int t = blockIdx.x;
    if (t >= N_REG) return;

    int m0, n0;
    tile_coords(t, m0, n0);
    int tn = t + grid;
    int m1 = 0, n1 = 0;
    if (tn < N_REG) tile_coords(tn, m1, n1);

    int my_tiles = (N_REG - 1 - t) / grid + 1;
    int total_gi = my_tiles * KITERS;            // multiple of 64 (even)

    // ldmatrix lane address decomposition (b16, k16 step = 32 bytes)
    uint32_t xorv = (uint32_t)rl << 4;
    uint32_t arow0 = (uint32_t)((q & 1) * 8 + rl);
    uint32_t acolq = (uint32_t)((q >> 1) * 16);
    uint32_t brow0 = (uint32_t)(warpN * 64 + (q >> 1) * 8 + rl);
    uint32_t bcolq = (uint32_t)((q & 1) * 16);

    float c[4][8][4];
#pragma unroll
    for (int i = 0; i < 4; i++)
#pragma unroll
        for (int j = 0; j < 8; j++)
#pragma unroll
            for (int k = 0; k < 4; k++) c[i][j][k] = 0.0f;

    // prologue: B(0) group, then A chunk {0,1} group -> pending = both at gi=0
    load_B(0, 0, n0, b_smem, wid, lane);
    cp_commit();
    load_A(0, 0, m0, a_smem, tid);
    load_A(1, 1, m0, a_smem, tid);
    cp_commit();

    int g = lane >> 2, tig = lane & 3;   // epilogue decomposition

#pragma unroll 1
    for (int gi = 0; gi < total_gi; gi++) {
        int k = gi & (KITERS - 1);
        int sub = gi & 3;
        int sbb = gi & 1;
        bool odd = (gi & 1) != 0;
        bool last_in_tile = (k == KITERS - 1);
        bool have_next = (gi + 1 < total_gi);
        uint32_t abase = a_smem + sub * A_SUB;
        uint32_t bbase = b_smem + sbb * B_STAGE;

        // ---- single wait: drains everything committed during gi-1 ----
        cp_wait<0>();
        __syncwarp();               // my warp's B(gi) slice + A data (own) resident

        // B phase (warp-private; ahead of the CTA barrier)
        uint32_t b0[4][4];
        {
            uint32_t colB = bcolq ^ xorv;
#pragma unroll
            for (int nb = 0; nb < 4; nb++)
                ldsm4(b0[nb], bbase + (brow0 + nb * 16) * 128 + colB);
        }
        if (have_next) {
            int ln0 = last_in_tile ? n1 : n0;
            load_B((k + 1) & (KITERS - 1), (gi + 1) & 1, ln0, b_smem, wid, lane);
        }
        cp_commit();                // B(gi+1) group (possibly empty)

        // CTA barrier only at even gi
        if (!odd) __syncthreads();

        // A ks=0 fragments, then (odd gi) issue next A chunk
        uint32_t a0[4][4];
        {
            uint32_t colA = acolq ^ xorv;
#pragma unroll
            for (int mt = 0; mt < 4; mt++)
                ldsm4(a0[mt], abase + (arow0 + mt * 16) * 128 + colA);
        }
        if (odd && have_next) {
            int lm0 = last_in_tile ? m1 : m0;
            int kk = (k + 1) & (KITERS - 1);
            int sub2 = (gi + 1) & 3;            // even: {0,1} or {2,3}
            load_A(kk, sub2, lm0, a_smem, tid);
            load_A(kk + 1, sub2 + 1, lm0, a_smem, tid);
        }
        cp_commit();                // A group (possibly empty)

        // ---- ks = 0 (both operands prefetched) ----
#pragma unroll
        for (int mt = 0; mt < 4; mt++)
#pragma unroll
            for (int nb = 0; nb < 4; nb++) {
                mma_f16(c[mt][nb * 2 + 0], a0[mt], b0[nb][0], b0[nb][1]);
                mma_f16(c[mt][nb * 2 + 1], a0[mt], b0[nb][2], b0[nb][3]);
            }
        // ---- ks = 1..3 ----
#pragma unroll
        for (int ks = 1; ks < 4; ks++) {
            uint32_t colA = ((uint32_t)(ks * 32) + acolq) ^ xorv;
            uint32_t colB = ((uint32_t)(ks * 32) + bcolq) ^ xorv;
            uint32_t a[4][4], b[4][4];
#pragma unroll
            for (int mt = 0; mt < 4; mt++)
                ldsm4(a[mt], abase + (arow0 + mt * 16) * 128 + colA);
#pragma unroll
            for (int nb = 0; nb < 4; nb++)
                ldsm4(b[nb], bbase + (brow0 + nb * 16) * 128 + colB);
#pragma unroll
            for (int mt = 0; mt < 4; mt++)
#pragma unroll
                for (int nb = 0; nb < 4; nb++) {
                    mma_f16(c[mt][nb * 2 + 0], a[mt], b[nb][0], b[nb][1]);
                    mma_f16(c[mt][nb * 2 + 1], a[mt], b[nb][2], b[nb][3]);
                }
        }

        // ---- tile epilogue: streaming stores (keep output out of L2) ----
        if (last_in_tile) {
#pragma unroll
            for (int nt = 0; nt < 8; nt++) {
                int col = n0 + warpN * 64 + nt * 8 + tig * 2;
                float bx = __ldg(bias + col);
                float by = __ldg(bias + col + 1);
#pragma unroll
                for (int mt = 0; mt < 4; mt++) {
                    size_t row = (size_t)m0 + mt * 16 + g;
                    float2 v0 = make_float2(c[mt][nt][0] + bx, c[mt][nt][1] + by);
                    float2 v1 = make_float2(c[mt][nt][2] + bx, c[mt][nt][3] + by);
                    __stcs(reinterpret_cast<float2*>(out + row * N_TOTAL + col), v0);
                    __stcs(reinterpret_cast<float2*>(out + (row + 8) * N_TOTAL + col), v1);
                    c[mt][nt][0] = 0.0f; c[mt][nt][1] = 0.0f;
                    c[mt][nt][2] = 0.0f; c[mt][nt][3] = 0.0f;
                }
            }
            m0 = m1; n0 = n1;
            tn += grid;
            if (tn < N_REG) tile_coords(tn, m1, n1);
        }
    }
}

// ---------------------------------------------------------------------------
// Kernel 3: split-K tail over the REM remainder tiles (separate kernel, all
// constants compile-time).  Piece t covers tile N_REG + t/SPLIT, kiters
// [(t%SPLIT)*PK, +PK).  Accumulates into the bias-initialized output.
// ---------------------------------------------------------------------------
__global__ void __launch_bounds__(THREADS, 2) gemm_tail_kernel(float* __restrict__ out) {
    extern __shared__ char smem[];
    uint32_t sb = (smem_u32(smem) + 1023u) & ~1023u;
    uint32_t a_smem = sb;
    uint32_t b_smem = sb + 4 * A_SUB;

    int tid = threadIdx.x;
    int lane = tid & 31, wid = tid >> 5;
    int warpN = wid;
    int q = lane >> 3, rl = lane & 7;
    int t = blockIdx.x;

    uint32_t xorv = (uint32_t)rl << 4;
    uint32_t arow0 = (uint32_t)((q & 1) * 8 + rl);
    uint32_t acolq = (uint32_t)((q >> 1) * 16);
    uint32_t brow0 = (uint32_t)(warpN * 64 + (q >> 1) * 8 + rl);
    uint32_t bcolq = (uint32_t)((q & 1) * 16);
    int g = lane >> 2, tig = lane & 3;

    int pm0, pn0;
    tile_coords(N_REG + t / SPLIT, pm0, pn0);
    int koff = (t % SPLIT) * PK;

    float c[4][8][4];
#pragma unroll
    for (int i = 0; i < 4; i++)
#pragma unroll
        for (int j = 0; j < 8; j++)
#pragma unroll
            for (int k = 0; k < 4; k++) c[i][j][k] = 0.0f;

    load_B(koff, 0, pn0, b_smem, wid, lane);
    cp_commit();
    load_A(koff, 0, pm0, a_smem, tid);
    load_A(koff + 1, 1, pm0, a_smem, tid);
    cp_commit();

#pragma unroll 1
    for (int gi = 0; gi < PK; gi++) {
        int sub = gi & 3;
        int sbb = gi & 1;
        bool odd = (gi & 1) != 0;
        bool have_next = (gi + 1 < PK);
        uint32_t abase = a_smem + sub * A_SUB;
        uint32_t bbase = b_smem + sbb * B_STAGE;

        cp_wait<0>();
        __syncwarp();

        uint32_t b0[4][4];
        {
            uint32_t colB = bcolq ^ xorv;
#pragma unroll
            for (int nb = 0; nb < 4; nb++)
                ldsm4(b0[nb], bbase + (brow0 + nb * 16) * 128 + colB);
        }
        if (have_next) load_B(koff + gi + 1, (gi + 1) & 1, pn0, b_smem, wid, lane);
        cp_commit();

        if (!odd) __syncthreads();

        uint32_t a0[4][4];
        {
            uint32_t colA = acolq ^ xorv;
#pragma unroll
            for (int mt = 0; mt < 4; mt++)
                ldsm4(a0[mt], abase + (arow0 + mt * 16) * 128 + colA);
        }
        if (odd && have_next) {
            int sub2 = (gi + 1) & 3;
            load_A(koff + gi + 1, sub2, pm0, a_smem, tid);
            load_A(koff + gi + 2, sub2 + 1, pm0, a_smem, tid);
        }
        cp_commit();

#pragma unroll
        for (int mt = 0; mt < 4; mt++)
#pragma unroll
            for (int nb = 0; nb < 4; nb++) {
                mma_f16(c[mt][nb * 2 + 0], a0[mt], b0[nb][0], b0[nb][1]);
                mma_f16(c[mt][nb * 2 + 1], a0[mt], b0[nb][2], b0[nb][3]);
            }
#pragma unroll
        for (int ks = 1; ks < 4; ks++) {
            uint32_t colA = ((uint32_t)(ks * 32) + acolq) ^ xorv;
            uint32_t colB = ((uint32_t)(ks * 32) + bcolq) ^ xorv;
            uint32_t a[4][4], b[4][4];
#pragma unroll
            for (int mt = 0; mt < 4; mt++)
                ldsm4(a[mt], abase + (arow0 + mt * 16) * 128 + colA);
#pragma unroll
            for (int nb = 0; nb < 4; nb++)
                ldsm4(b[nb], bbase + (brow0 + nb * 16) * 128 + colB);
#pragma unroll
            for (int mt = 0; mt < 4; mt++)
#pragma unroll
                for (int nb = 0; nb < 4; nb++) {
                    mma_f16(c[mt][nb * 2 + 0], a[mt], b[nb][0], b[nb][1]);
                    mma_f16(c[mt][nb * 2 + 1], a[mt], b[nb][2], b[nb][3]);
                }
        }
    }

    // piece epilogue: accumulate into bias-initialized output
#pragma unroll
    for (int nt = 0; nt < 8; nt++) {
        int col = pn0 + warpN * 64 + nt * 8 + tig * 2;
#pragma unroll
        for (int mt = 0; mt < 4; mt++) {
            size_t row = (size_t)pm0 + mt * 16 + g;
            atomicAdd(out + row * N_TOTAL + col,           c[mt][nt][0]);
            atomicAdd(out + row * N_TOTAL + col + 1,       c[mt][nt][1]);
            atomicAdd(out + (row + 8) * N_TOTAL + col,     c[mt][nt][2]);
            atomicAdd(out + (row + 8) * N_TOTAL + col + 1, c[mt][nt][3]);
        }
    }
}

// ---------------------------------------------------------------------------
// Launch
// ---------------------------------------------------------------------------
extern "C" void kernel_launch(void* const* d_in, const int* in_sizes, int n_in,
                              void* d_out, int out_size) {
    const float* x = nullptr;
    const int* wq = nullptr;
    const float* ws = nullptr;
    const float* bias = nullptr;
    for (int i = 0; i < n_in; i++) {
        switch (in_sizes[i]) {
            case 33554432: x    = (const float*)d_in[i]; break;  // 4*2048*4096
            case 45088768: wq   = (const int*)d_in[i];   break;  // 11008*4096
            case 352256:   ws   = (const float*)d_in[i]; break;  // groups
            case 11008:    bias = (const float*)d_in[i]; break;
        }
    }

    cudaFuncSetAttribute(gemm_f16_kernel,
                         cudaFuncAttributeMaxDynamicSharedMemorySize, SMEM_BYTES);
    cudaFuncSetAttribute(gemm_tail_kernel,
                         cudaFuncAttributeMaxDynamicSharedMemorySize, SMEM_BYTES);

    prepass_kernel<<<X_BLOCKS + W_BLOCKS + REM * 16, 256>>>(x, wq, ws, bias,
                                                            (float*)d_out);

    gemm_tail_kernel<<<PIECES, THREADS, SMEM_BYTES>>>((float*)d_out);

    gemm_f16_kernel<<<GRID, THREADS, SMEM_BYTES>>>(bias, (float*)d_out);
    (void)out_size;
}

// round 17
// speedup vs baseline: 1.0727x; 1.0022x over previous
#include <cuda_runtime.h>
#include <cuda_fp16.h>
#include <cstdint>

// ---------------------------------------------------------------------------
// Problem constants (ALL compile-time; GB300 = 152 SMs -> GRID = 304)
// ---------------------------------------------------------------------------
static constexpr int M_TOTAL = 8192;      // 4 * 2048
static constexpr int N_TOTAL = 11008;
static constexpr int K_TOTAL = 4096;

static constexpr int BM = 64;
static constexpr int BN = 256;
static constexpr int BK = 64;                 // fp16 -> 128 B per row
static constexpr int KITERS = K_TOTAL / BK;   // 64
static constexpr int THREADS = 128;           // 4 warps, 2 CTAs per SM

static constexpr int A_SUB = BM * BK * 2;     // 8 KB per kiter sub-buffer
static constexpr int B_STAGE = BN * BK * 2;   // 32 KB
static constexpr int SMEM_BYTES = 4 * A_SUB + 2 * B_STAGE + 1024;  // 99328 -> 2 CTAs/SM

static constexpr int PID_N = N_TOTAL / BN;    // 43
static constexpr int GROUP_M = 16;            // CTA raster group (wave set ~46MB < L2)
static constexpr int N_TILES = (M_TOTAL / BM) * PID_N;   // 5504

static constexpr int GRID = 304;              // 2 CTAs x 152 SMs
static constexpr int N_REG = (N_TILES / GRID) * GRID;    // 5472 = 18*304
static constexpr int REM = N_TILES - N_REG;   // 32 remainder tiles
static constexpr int SPLIT = 8;               // split-K ways -> 256 pieces
static constexpr int PIECES = REM * SPLIT;    // 256 (<= GRID: one wave)
static constexpr int PK = KITERS / SPLIT;     // 8 kiters per piece (even)

// prepass: 2 x 16B units per thread
static constexpr int X_UNITS = 33554432 / 4;          // 8388608 float4
static constexpr int W_UNITS = 45088768 / 4;          // 11272192 int4
static constexpr int X_BLOCKS = X_UNITS / 2 / 256;    // 16384
static constexpr int W_BLOCKS = W_UNITS / 2 / 256;    // 22016

// ---------------------------------------------------------------------------
// Scratch (device globals: allocation-free)
// ---------------------------------------------------------------------------
__device__ __half g_xh[(size_t)M_TOTAL * K_TOTAL];   // 67 MB, fp16 x
__device__ __half g_wh[(size_t)N_TOTAL * K_TOTAL];   // 90 MB, fp16 dequant W

__constant__ float c_nf4[16] = {
    -1.0f, -0.6961928009986877f, -0.5250730514526367f, -0.39491748809814453f,
    -0.28444138169288635f, -0.18477343022823334f, -0.09105003625154495f, 0.0f,
    0.07958029955625534f, 0.16093020141124725f, 0.24611230194568634f,
    0.33791524171829224f, 0.44070982933044434f, 0.5626170039176941f,
    0.7229568362236023f, 1.0f};

// ---------------------------------------------------------------------------
// Helpers (baseline PTX only; sm_103 virtual target has no tcgen05)
// ---------------------------------------------------------------------------
__device__ __forceinline__ uint32_t smem_u32(const void* p) {
    uint32_t a;
    asm("{ .reg .u64 t; cvta.to.shared.u64 t, %1; cvt.u32.u64 %0, t; }" : "=r"(a) : "l"(p));
    return a;
}

__device__ __forceinline__ void cp16(uint32_t dst, const void* src) {
    asm volatile("cp.async.cg.shared.global [%0], [%1], 16;" :: "r"(dst), "l"(src));
}
__device__ __forceinline__ void cp_commit() {
    asm volatile("cp.async.commit_group;" ::: "memory");
}
template <int N>
__device__ __forceinline__ void cp_wait() {
    asm volatile("cp.async.wait_group %0;" :: "n"(N) : "memory");
}

__device__ __forceinline__ void ldsm4(uint32_t* r, uint32_t addr) {
    asm volatile("ldmatrix.sync.aligned.m8n8.x4.shared.b16 {%0,%1,%2,%3}, [%4];"
                 : "=r"(r[0]), "=r"(r[1]), "=r"(r[2]), "=r"(r[3]) : "r"(addr));
}

__device__ __forceinline__ void mma_f16(float* c, const uint32_t* a,
                                        uint32_t b0, uint32_t b1) {
    asm volatile(
        "mma.sync.aligned.m16n8k16.row.col.f32.f16.f16.f32 "
        "{%0,%1,%2,%3}, {%4,%5,%6,%7}, {%8,%9}, {%0,%1,%2,%3};"
        : "+f"(c[0]), "+f"(c[1]), "+f"(c[2]), "+f"(c[3])
        : "r"(a[0]), "r"(a[1]), "r"(a[2]), "r"(a[3]), "r"(b0), "r"(b1));
}

// SW128 swizzle on (row*128 + colb)
#define SWZ(row, colb) ((uint32_t)(row) * 128u + ((uint32_t)(colb) ^ ((((uint32_t)(row)) & 7u) << 4)))

// grouped rasterization: GROUP_M m-tiles share each B n-column within a wave
__device__ __forceinline__ void tile_coords(int t, int& m0, int& n0) {
    int group = t / (GROUP_M * PID_N);
    int local = t % (GROUP_M * PID_N);
    int pid_m = group * GROUP_M + (local & (GROUP_M - 1));
    int pid_n = local >> 4;                    // GROUP_M = 16
    m0 = pid_m * BM;
    n0 = pid_n * BN;
}

// ---------------------------------------------------------------------------
// Kernel 1 (fused prepass): x -> fp16, NF4 dequant W -> fp16, and init the
// REM remainder tiles' output region to bias (split-K pieces atomicAdd into it).
// ---------------------------------------------------------------------------
__global__ void __launch_bounds__(256) prepass_kernel(const float* __restrict__ x,
                                                      const int* __restrict__ q,
                                                      const float* __restrict__ sc,
                                                      const float* __restrict__ bias,
                                                      float* __restrict__ out) {
    if (blockIdx.x < X_BLOCKS) {
        size_t i = ((size_t)blockIdx.x * 256 + threadIdx.x) * 2;   // float4 index
        float4 v0 = reinterpret_cast<const float4*>(x)[i];
        float4 v1 = reinterpret_cast<const float4*>(x)[i + 1];
        __half2 a0 = __floats2half2_rn(v0.x, v0.y);
        __half2 a1 = __floats2half2_rn(v0.z, v0.w);
        __half2 a2 = __floats2half2_rn(v1.x, v1.y);
        __half2 a3 = __floats2half2_rn(v1.z, v1.w);
        uint4 o = make_uint4(*reinterpret_cast<uint32_t*>(&a0),
                             *reinterpret_cast<uint32_t*>(&a1),
                             *reinterpret_cast<uint32_t*>(&a2),
                             *reinterpret_cast<uint32_t*>(&a3));
        reinterpret_cast<uint4*>(g_xh)[i >> 1] = o;
    } else if (blockIdx.x < X_BLOCKS + W_BLOCKS) {
        float tv = c_nf4[threadIdx.x & 15];                  // lane l holds nf4[l&15]
        size_t i = ((size_t)(blockIdx.x - X_BLOCKS) * 256 + threadIdx.x) * 2; // int4 idx
        int4 q0 = reinterpret_cast<const int4*>(q)[i];
        int4 q1 = reinterpret_cast<const int4*>(q)[i + 1];
        float s = __ldg(sc + (i >> 5));      // packs 2j,2j+1 share the 128-elem group
        float w0 = __shfl_sync(0xffffffffu, tv, q0.x & 15) * s;
        float w1 = __shfl_sync(0xffffffffu, tv, q0.y & 15) * s;
        float w2 = __shfl_sync(0xffffffffu, tv, q0.z & 15) * s;
        float w3 = __shfl_sync(0xffffffffu, tv, q0.w & 15) * s;
        float w4 = __shfl_sync(0xffffffffu, tv, q1.x & 15) * s;
        float w5 = __shfl_sync(0xffffffffu, tv, q1.y & 15) * s;
        float w6 = __shfl_sync(0xffffffffu, tv, q1.z & 15) * s;
        float w7 = __shfl_sync(0xffffffffu, tv, q1.w & 15) * s;
        __half2 a0 = __floats2half2_rn(w0, w1);
        __half2 a1 = __floats2half2_rn(w2, w3);
        __half2 a2 = __floats2half2_rn(w4, w5);
        __half2 a3 = __floats2half2_rn(w6, w7);
        uint4 o = make_uint4(*reinterpret_cast<uint32_t*>(&a0),
                             *reinterpret_cast<uint32_t*>(&a1),
                             *reinterpret_cast<uint32_t*>(&a2),
                             *reinterpret_cast<uint32_t*>(&a3));
        reinterpret_cast<uint4*>(g_wh)[i >> 1] = o;
    } else {
        // init remainder tile r output to bias: 16 blocks per tile, 1 float4/thr
        int bid2 = blockIdx.x - X_BLOCKS - W_BLOCKS;
        int r = bid2 >> 4;
        int inner = ((bid2 & 15) << 8) + threadIdx.x;    // 0..4095
        int m0, n0;
        tile_coords(N_REG + r, m0, n0);
        int row = inner >> 6;                            // 0..63
        int c4 = (inner & 63) << 2;                      // col offset 0..252
        int col = n0 + c4;
        float4 v = make_float4(__ldg(bias + col), __ldg(bias + col + 1),
                               __ldg(bias + col + 2), __ldg(bias + col + 3));
        *reinterpret_cast<float4*>(out + (size_t)(m0 + row) * N_TOTAL + col) = v;
    }
}

// ---------------------------------------------------------------------------
// Shared tile-load helpers
// ---------------------------------------------------------------------------
__device__ __forceinline__ void load_A(int kiter, int sub, int m0,
                                       uint32_t a_smem, int tid) {
    const __half* asrc = g_xh + (size_t)m0 * K_TOTAL + kiter * BK;
    uint32_t adst = a_smem + sub * A_SUB;
#pragma unroll
    for (int it = 0; it < 4; it++) {                 // 512 16B chunks / 128 thr
        int idx = tid + it * THREADS;
        int r = idx >> 3, ch = idx & 7;
        cp16(adst + SWZ(r, ch * 16), asrc + (size_t)r * K_TOTAL + ch * 8);
    }
}

// warp-sliced: warp w loads (and later reads) only B rows [64w, 64w+64)
__device__ __forceinline__ void load_B(int kiter, int s, int n0,
                                       uint32_t b_smem, int wid, int lane) {
    const __half* bsrc = g_wh + (size_t)n0 * K_TOTAL + kiter * BK;
    uint32_t bdst = b_smem + s * B_STAGE;
#pragma unroll
    for (int it = 0; it < 16; it++) {                // 512 chunks / 32 lanes
        int c = lane + it * 32;
        int r = wid * 64 + (c >> 3), ch = c & 7;
        cp16(bdst + SWZ(r, ch * 16), bsrc + (size_t)r * K_TOTAL + ch * 8);
    }
}

// ---------------------------------------------------------------------------
// Kernel 2: persistent mma.sync fp16 GEMM over the first N_REG tiles.
// R13/R16 structure verbatim (all-constexpr boundaries).
// ---------------------------------------------------------------------------
__global__ void __launch_bounds__(THREADS, 2) gemm_f16_kernel(const float* __restrict__ bias,
                                                              float* __restrict__ out) {
    extern __shared__ char smem[];
    uint32_t sb = (smem_u32(smem) + 1023u) & ~1023u;
    uint32_t a_smem = sb;
    uint32_t b_smem = sb + 4 * A_SUB;

    int tid = threadIdx.x;
    int lane = tid & 31, wid = tid >> 5;
    int warpN = wid;               // 4 warps along N, 1 along M
    int q = lane >> 3, rl = lane & 7;

    int grid = gridDim.x;
    int t = blockIdx.x;
    if (t >= N_REG) return;

    int m0, n0;
    tile_coords(t, m0, n0);
    int tn = t + grid;
    int m1 = 0, n1 = 0;
    if (tn < N_REG) tile_coords(tn, m1, n1);

    int my_tiles = (N_REG - 1 - t) / grid + 1;
    int total_gi = my_tiles * KITERS;            // multiple of 64 (even)

    // ldmatrix lane address decomposition (b16, k16 step = 32 bytes)
    uint32_t xorv = (uint32_t)rl << 4;
    uint32_t arow0 = (uint32_t)((q & 1) * 8 + rl);
    uint32_t acolq = (uint32_t)((q >> 1) * 16);
    uint32_t brow0 = (uint32_t)(warpN * 64 + (q >> 1) * 8 + rl);
    uint32_t bcolq = (uint32_t)((q & 1) * 16);

    float c[4][8][4];
#pragma unroll
    for (int i = 0; i < 4; i++)
#pragma unroll
        for (int j = 0; j < 8; j++)
#pragma unroll
            for (int k = 0; k < 4; k++) c[i][j][k] = 0.0f;

    // prologue: B(0) group, then A chunk {0,1} group -> pending = both at gi=0
    load_B(0, 0, n0, b_smem, wid, lane);
    cp_commit();
    load_A(0, 0, m0, a_smem, tid);
    load_A(1, 1, m0, a_smem, tid);
    cp_commit();

    int g = lane >> 2, tig = lane & 3;   // epilogue decomposition

#pragma unroll 1
    for (int gi = 0; gi < total_gi; gi++) {
        int k = gi & (KITERS - 1);
        int sub = gi & 3;
        int sbb = gi & 1;
        bool odd = (gi & 1) != 0;
        bool last_in_tile = (k == KITERS - 1);
        bool have_next = (gi + 1 < total_gi);
        uint32_t abase = a_smem + sub * A_SUB;
        uint32_t bbase = b_smem + sbb * B_STAGE;

        // ---- single wait: drains everything committed during gi-1 ----
        cp_wait<0>();
        __syncwarp();               // my warp's B(gi) slice + A data (own) resident

        // B phase (warp-private; ahead of the CTA barrier)
        uint32_t b0[4][4];
        {
            uint32_t colB = bcolq ^ xorv;
#pragma unroll
            for (int nb = 0; nb < 4; nb++)
                ldsm4(b0[nb], bbase + (brow0 + nb * 16) * 128 + colB);
        }
        if (have_next) {
            int ln0 = last_in_tile ? n1 : n0;
            load_B((k + 1) & (KITERS - 1), (gi + 1) & 1, ln0, b_smem, wid, lane);
        }
        cp_commit();                // B(gi+1) group (possibly empty)

        // CTA barrier only at even gi
        if (!odd) __syncthreads();

        // A ks=0 fragments, then (odd gi) issue next A chunk
        uint32_t a0[4][4];
        {
            uint32_t colA = acolq ^ xorv;
#pragma unroll
            for (int mt = 0; mt < 4; mt++)
                ldsm4(a0[mt], abase + (arow0 + mt * 16) * 128 + colA);
        }
        if (odd && have_next) {
            int lm0 = last_in_tile ? m1 : m0;
            int kk = (k + 1) & (KITERS - 1);
            int sub2 = (gi + 1) & 3;            // even: {0,1} or {2,3}
            load_A(kk, sub2, lm0, a_smem, tid);
            load_A(kk + 1, sub2 + 1, lm0, a_smem, tid);
        }
        cp_commit();                // A group (possibly empty)

        // ---- ks = 0 (both operands prefetched) ----
#pragma unroll
        for (int mt = 0; mt < 4; mt++)
#pragma unroll
            for (int nb = 0; nb < 4; nb++) {
                mma_f16(c[mt][nb * 2 + 0], a0[mt], b0[nb][0], b0[nb][1]);
                mma_f16(c[mt][nb * 2 + 1], a0[mt], b0[nb][2], b0[nb][3]);
            }
        // ---- ks = 1..3 ----
#pragma unroll
        for (int ks = 1; ks < 4; ks++) {
            uint32_t colA = ((uint32_t)(ks * 32) + acolq) ^ xorv;
            uint32_t colB = ((uint32_t)(ks * 32) + bcolq) ^ xorv;
            uint32_t a[4][4], b[4][4];
#pragma unroll
            for (int mt = 0; mt < 4; mt++)
                ldsm4(a[mt], abase + (arow0 + mt * 16) * 128 + colA);
#pragma unroll
            for (int nb = 0; nb < 4; nb++)
                ldsm4(b[nb], bbase + (brow0 + nb * 16) * 128 + colB);
#pragma unroll
            for (int mt = 0; mt < 4; mt++)
#pragma unroll
                for (int nb = 0; nb < 4; nb++) {
                    mma_f16(c[mt][nb * 2 + 0], a[mt], b[nb][0], b[nb][1]);
                    mma_f16(c[mt][nb * 2 + 1], a[mt], b[nb][2], b[nb][3]);
                }
        }

        // ---- tile epilogue: streaming stores (keep output out of L2) ----
        if (last_in_tile) {
#pragma unroll
            for (int nt = 0; nt < 8; nt++) {
                int col = n0 + warpN * 64 + nt * 8 + tig * 2;
                float bx = __ldg(bias + col);
                float by = __ldg(bias + col + 1);
#pragma unroll
                for (int mt = 0; mt < 4; mt++) {
                    size_t row = (size_t)m0 + mt * 16 + g;
                    float2 v0 = make_float2(c[mt][nt][0] + bx, c[mt][nt][1] + by);
                    float2 v1 = make_float2(c[mt][nt][2] + bx, c[mt][nt][3] + by);
                    __stcs(reinterpret_cast<float2*>(out + row * N_TOTAL + col), v0);
                    __stcs(reinterpret_cast<float2*>(out + (row + 8) * N_TOTAL + col), v1);
                    c[mt][nt][0] = 0.0f; c[mt][nt][1] = 0.0f;
                    c[mt][nt][2] = 0.0f; c[mt][nt][3] = 0.0f;
                }
            }
            m0 = m1; n0 = n1;
            tn += grid;
            if (tn < N_REG) tile_coords(tn, m1, n1);
        }
    }
}

// ---------------------------------------------------------------------------
// Kernel 3: split-K tail over the REM remainder tiles (separate kernel, all
// constants compile-time).  Piece t covers tile N_REG + t/SPLIT, kiters
// [(t%SPLIT)*PK, +PK).  Accumulates into the bias-initialized output.
// ---------------------------------------------------------------------------
__global__ void __launch_bounds__(THREADS, 2) gemm_tail_kernel(float* __restrict__ out) {
    extern __shared__ char smem[];
    uint32_t sb = (smem_u32(smem) + 1023u) & ~1023u;
    uint32_t a_smem = sb;
    uint32_t b_smem = sb + 4 * A_SUB;

    int tid = threadIdx.x;
    int lane = tid & 31, wid = tid >> 5;
    int warpN = wid;
    int q = lane >> 3, rl = lane & 7;
    int t = blockIdx.x;

    uint32_t xorv = (uint32_t)rl << 4;
    uint32_t arow0 = (uint32_t)((q & 1) * 8 + rl);
    uint32_t acolq = (uint32_t)((q >> 1) * 16);
    uint32_t brow0 = (uint32_t)(warpN * 64 + (q >> 1) * 8 + rl);
    uint32_t bcolq = (uint32_t)((q & 1) * 16);
    int g = lane >> 2, tig = lane & 3;

    int pm0, pn0;
    tile_coords(N_REG + t / SPLIT, pm0, pn0);
    int koff = (t % SPLIT) * PK;

    float c[4][8][4];
#pragma unroll
    for (int i = 0; i < 4; i++)
#pragma unroll
        for (int j = 0; j < 8; j++)
#pragma unroll
            for (int k = 0; k < 4; k++) c[i][j][k] = 0.0f;

    load_B(koff, 0, pn0, b_smem, wid, lane);
    cp_commit();
    load_A(koff, 0, pm0, a_smem, tid);
    load_A(koff + 1, 1, pm0, a_smem, tid);
    cp_commit();

#pragma unroll 1
    for (int gi = 0; gi < PK; gi++) {
        int sub = gi & 3;
        int sbb = gi & 1;
        bool odd = (gi & 1) != 0;
        bool have_next = (gi + 1 < PK);
        uint32_t abase = a_smem + sub * A_SUB;
        uint32_t bbase = b_smem + sbb * B_STAGE;

        cp_wait<0>();
        __syncwarp();

        uint32_t b0[4][4];
        {
            uint32_t colB = bcolq ^ xorv;
#pragma unroll
            for (int nb = 0; nb < 4; nb++)
                ldsm4(b0[nb], bbase + (brow0 + nb * 16) * 128 + colB);
        }
        if (have_next) load_B(koff + gi + 1, (gi + 1) & 1, pn0, b_smem, wid, lane);
        cp_commit();

        if (!odd) __syncthreads();

        uint32_t a0[4][4];
        {
            uint32_t colA = acolq ^ xorv;
#pragma unroll
            for (int mt = 0; mt < 4; mt++)
                ldsm4(a0[mt], abase + (arow0 + mt * 16) * 128 + colA);
        }
        if (odd && have_next) {
            int sub2 = (gi + 1) & 3;
            load_A(koff + gi + 1, sub2, pm0, a_smem, tid);
            load_A(koff + gi + 2, sub2 + 1, pm0, a_smem, tid);
        }
        cp_commit();

#pragma unroll
        for (int mt = 0; mt < 4; mt++)
#pragma unroll
            for (int nb = 0; nb < 4; nb++) {
                mma_f16(c[mt][nb * 2 + 0], a0[mt], b0[nb][0], b0[nb][1]);
                mma_f16(c[mt][nb * 2 + 1], a0[mt], b0[nb][2], b0[nb][3]);
            }
#pragma unroll
        for (int ks = 1; ks < 4; ks++) {
            uint32_t colA = ((uint32_t)(ks * 32) + acolq) ^ xorv;
            uint32_t colB = ((uint32_t)(ks * 32) + bcolq) ^ xorv;
            uint32_t a[4][4], b[4][4];
#pragma unroll
            for (int mt = 0; mt < 4; mt++)
                ldsm4(a[mt], abase + (arow0 + mt * 16) * 128 + colA);
#pragma unroll
            for (int nb = 0; nb < 4; nb++)
                ldsm4(b[nb], bbase + (brow0 + nb * 16) * 128 + colB);
#pragma unroll
            for (int mt = 0; mt < 4; mt++)
#pragma unroll
                for (int nb = 0; nb < 4; nb++) {
                    mma_f16(c[mt][nb * 2 + 0], a[mt], b[nb][0], b[nb][1]);
                    mma_f16(c[mt][nb * 2 + 1], a[mt], b[nb][2], b[nb][3]);
                }
        }
    }

    // piece epilogue: accumulate into bias-initialized output
#pragma unroll
    for (int nt = 0; nt < 8; nt++) {
        int col = pn0 + warpN * 64 + nt * 8 + tig * 2;
#pragma unroll
        for (int mt = 0; mt < 4; mt++) {
            size_t row = (size_t)pm0 + mt * 16 + g;
            atomicAdd(out + row * N_TOTAL + col,           c[mt][nt][0]);
            atomicAdd(out + row * N_TOTAL + col + 1,       c[mt][nt][1]);
            atomicAdd(out + (row + 8) * N_TOTAL + col,     c[mt][nt][2]);
            atomicAdd(out + (row + 8) * N_TOTAL + col + 1, c[mt][nt][3]);
        }
    }
}

// ---------------------------------------------------------------------------
// Launch
// ---------------------------------------------------------------------------
extern "C" void kernel_launch(void* const* d_in, const int* in_sizes, int n_in,
                              void* d_out, int out_size) {
    const float* x = nullptr;
    const int* wq = nullptr;
    const float* ws = nullptr;
    const float* bias = nullptr;
    for (int i = 0; i < n_in; i++) {
        switch (in_sizes[i]) {
            case 33554432: x    = (const float*)d_in[i]; break;  // 4*2048*4096
            case 45088768: wq   = (const int*)d_in[i];   break;  // 11008*4096
            case 352256:   ws   = (const float*)d_in[i]; break;  // groups
            case 11008:    bias = (const float*)d_in[i]; break;
        }
    }

    cudaFuncSetAttribute(gemm_f16_kernel,
                         cudaFuncAttributeMaxDynamicSharedMemorySize, SMEM_BYTES);
    cudaFuncSetAttribute(gemm_tail_kernel,
                         cudaFuncAttributeMaxDynamicSharedMemorySize, SMEM_BYTES);

    prepass_kernel<<<X_BLOCKS + W_BLOCKS + REM * 16, 256>>>(x, wq, ws, bias,
                                                            (float*)d_out);

    gemm_tail_kernel<<<PIECES, THREADS, SMEM_BYTES>>>((float*)d_out);

    gemm_f16_kernel<<<GRID, THREADS, SMEM_BYTES>>>(bias, (float*)d_out);
    (void)out_size;
}